// round 5
// baseline (speedup 1.0000x reference)
#include <cuda_runtime.h>
#include <cuda_fp16.h>
#include <cstdint>

#define DEVI static __device__ __forceinline__

// ---------------- problem dims ----------------
constexpr int Bb = 16, Nq = 1024, Cc = 1024, Hh = 16, Dd = 64, Pp = 16;
constexpr int Ll = Pp + Nq;       // 1040 keys
constexpr int Mr = Bb * Nq;       // 16384 token rows

// ---------------- scratch (device globals; no allocs allowed) ----------------
__device__ __half g_xh[Mr * Cc];            // x in fp16
__device__ __half g_wqkvh[Cc * 3 * Cc];     // w_qkv fp16
__device__ __half g_wprojh[Cc * Cc];        // w_proj fp16
__device__ __half g_Q[Bb * Hh * Nq * Dd];   // [bh][n][d], pre-scaled by 0.125
__device__ __half g_K[Bb * Hh * Ll * Dd];   // [bh][p+n][d]
__device__ __half g_V[Bb * Hh * Ll * Dd];   // [bh][p+n][d]
__device__ __half g_AO[Mr * Cc];            // attention out, [b*N+n][h*64+d]

// ---------------- small helpers ----------------
DEVI void cp16(void* smem, const void* gmem) {
    uint32_t s = (uint32_t)__cvta_generic_to_shared(smem);
    asm volatile("cp.async.cg.shared.global [%0], [%1], 16;\n" :: "r"(s), "l"(gmem));
}
DEVI void cp_commit() { asm volatile("cp.async.commit_group;\n"); }
template <int n> DEVI void cp_wait() { asm volatile("cp.async.wait_group %0;\n" :: "n"(n)); }

DEVI void mma16816(float* c, uint32_t a0, uint32_t a1, uint32_t a2, uint32_t a3,
                   uint32_t b0, uint32_t b1) {
    asm volatile(
        "mma.sync.aligned.m16n8k16.row.col.f32.f16.f16.f32 "
        "{%0,%1,%2,%3},{%4,%5,%6,%7},{%8,%9},{%0,%1,%2,%3};\n"
        : "+f"(c[0]), "+f"(c[1]), "+f"(c[2]), "+f"(c[3])
        : "r"(a0), "r"(a1), "r"(a2), "r"(a3), "r"(b0), "r"(b1));
}

DEVI uint32_t pack2(float x, float y) {
    __half2 h = __floats2half2_rn(x, y);
    return *reinterpret_cast<uint32_t*>(&h);
}
DEVI float qmax(float v) {
    v = fmaxf(v, __shfl_xor_sync(0xffffffffu, v, 1));
    v = fmaxf(v, __shfl_xor_sync(0xffffffffu, v, 2));
    return v;
}
DEVI float qsum(float v) {
    v += __shfl_xor_sync(0xffffffffu, v, 1);
    v += __shfl_xor_sync(0xffffffffu, v, 2);
    return v;
}

// ---------------- fp32 -> fp16 conversion (x, w_qkv, w_proj in one pass) ----
constexpr int NX4 = (Mr * Cc) / 4;        // 4194304
constexpr int NQ4 = (Cc * 3 * Cc) / 4;    // 786432
constexpr int NP4 = (Cc * Cc) / 4;        // 262144

__global__ void convert_all(const float* __restrict__ x,
                            const float* __restrict__ wq,
                            const float* __restrict__ wp) {
    int i = blockIdx.x * blockDim.x + threadIdx.x;
    const float4* src;
    __half2* dst;
    int j;
    if (i < NX4)            { src = (const float4*)x;  dst = (__half2*)g_xh;     j = i; }
    else if (i < NX4 + NQ4) { src = (const float4*)wq; dst = (__half2*)g_wqkvh;  j = i - NX4; }
    else if (i < NX4 + NQ4 + NP4) { src = (const float4*)wp; dst = (__half2*)g_wprojh; j = i - NX4 - NQ4; }
    else return;
    float4 v = src[j];
    dst[2 * j]     = __floats2half2_rn(v.x, v.y);
    dst[2 * j + 1] = __floats2half2_rn(v.z, v.w);
}

// ---------------- scatter prefix pk/pv into K/V heads ----------------
__global__ void prefix_kernel(const float* __restrict__ pk, const float* __restrict__ pv) {
    int i = blockIdx.x * blockDim.x + threadIdx.x;   // over B*P*C = 262144
    if (i >= Bb * Pp * Cc) return;
    int c = i & (Cc - 1);
    int bp = i >> 10;
    int p = bp & (Pp - 1);
    int b = bp >> 4;
    int h = c >> 6, d = c & 63;
    int o = ((b * Hh + h) * Ll + p) * Dd + d;
    g_K[o] = __float2half(pk[i]);
    g_V[o] = __float2half(pv[i]);
}

// ---------------- GEMM epilogue for QKV scatter ----------------
DEVI void qkv_store(int m, int col, float v0, float v1) {
    int b = m >> 10, n = m & 1023;
    int s = col >> 10, cc = col & 1023;
    int h = cc >> 6, d = cc & 63;
    if (s == 0) {
        __half2 hv = __floats2half2_rn(v0 * 0.125f, v1 * 0.125f);  // fold softmax scale
        *(__half2*)(g_Q + (((size_t)(b * Hh + h)) * Nq + n) * Dd + d) = hv;
    } else {
        __half2 hv = __floats2half2_rn(v0, v1);
        __half* base = (s == 1) ? g_K : g_V;
        *(__half2*)(base + (((size_t)(b * Hh + h)) * Ll + Pp + n) * Dd + d) = hv;
    }
}

// ---------------- tiled GEMM: 128x128x32, 256 thr, double-buffered cp.async --
// EPI 0: C[16384,3072] = xh @ wqkvh, scatter to Q/K/V
// EPI 1: out[16384,1024] = AO @ wprojh + bias (fp32 out)
template <int EPI>
__global__ __launch_bounds__(256) void gemm_kernel(float* __restrict__ outp,
                                                   const float* __restrict__ bias) {
    const __half* __restrict__ A  = (EPI == 0) ? g_xh : g_AO;
    const __half* __restrict__ Bm = (EPI == 0) ? g_wqkvh : g_wprojh;
    const int Nc = (EPI == 0) ? 3 * Cc : Cc;
    const int K  = Cc;

    __shared__ __half As[2][128 * 40];   // [m][k] pad 8
    __shared__ __half Bs[2][32 * 136];   // [k][n] pad 8

    const int tid = threadIdx.x;
    const int wid = tid >> 5, lane = tid & 31;
    const int g = lane >> 2, t = lane & 3;
    const int wm = wid >> 2, wn = wid & 3;         // 2x4 warp grid, warp tile 64x32
    const int mBase = blockIdx.y * 128, nBase = blockIdx.x * 128;

    float acc[4][4][4];
#pragma unroll
    for (int i = 0; i < 4; i++)
#pragma unroll
        for (int j = 0; j < 4; j++)
#pragma unroll
            for (int r = 0; r < 4; r++) acc[i][j][r] = 0.f;

    auto prefetch = [&](int kt, int buf) {
#pragma unroll
        for (int j = 0; j < 2; j++) {
            int ci = tid + j * 256;
            int row = ci >> 2, cc = ci & 3;
            cp16(&As[buf][row * 40 + cc * 8],
                 A + (size_t)(mBase + row) * K + kt * 32 + cc * 8);
        }
#pragma unroll
        for (int j = 0; j < 2; j++) {
            int ci = tid + j * 256;
            int row = ci >> 4, cc = ci & 15;
            cp16(&Bs[buf][row * 136 + cc * 8],
                 Bm + (size_t)(kt * 32 + row) * Nc + nBase + cc * 8);
        }
    };

    const int nk = K >> 5;   // 32
    prefetch(0, 0);
    cp_commit();
    for (int kt = 0; kt < nk; kt++) {
        if (kt + 1 < nk) { prefetch(kt + 1, (kt + 1) & 1); cp_commit(); cp_wait<1>(); }
        else             { cp_wait<0>(); }
        __syncthreads();
        const __half* as = As[kt & 1];
        const __half* bs = Bs[kt & 1];
#pragma unroll
        for (int ks = 0; ks < 2; ks++) {
            uint32_t af[4][4];
#pragma unroll
            for (int mi = 0; mi < 4; mi++) {
                int r0 = wm * 64 + mi * 16 + g;
                const __half* ap = as + r0 * 40 + ks * 16 + 2 * t;
                af[mi][0] = *(const uint32_t*)(ap);
                af[mi][1] = *(const uint32_t*)(ap + 8 * 40);
                af[mi][2] = *(const uint32_t*)(ap + 8);
                af[mi][3] = *(const uint32_t*)(ap + 8 * 40 + 8);
            }
#pragma unroll
            for (int ni = 0; ni < 4; ni++) {
                int col = wn * 32 + ni * 8 + g;
                int kr = ks * 16 + 2 * t;
                uint32_t b0 = (uint32_t)*(const uint16_t*)(bs + kr * 136 + col)
                            | ((uint32_t)*(const uint16_t*)(bs + (kr + 1) * 136 + col) << 16);
                uint32_t b1 = (uint32_t)*(const uint16_t*)(bs + (kr + 8) * 136 + col)
                            | ((uint32_t)*(const uint16_t*)(bs + (kr + 9) * 136 + col) << 16);
#pragma unroll
                for (int mi = 0; mi < 4; mi++)
                    mma16816(acc[mi][ni], af[mi][0], af[mi][1], af[mi][2], af[mi][3], b0, b1);
            }
        }
        __syncthreads();
    }

    // epilogue
#pragma unroll
    for (int mi = 0; mi < 4; mi++) {
#pragma unroll
        for (int ni = 0; ni < 4; ni++) {
            int m = mBase + wm * 64 + mi * 16 + g;
            int col = nBase + wn * 32 + ni * 8 + 2 * t;
            if (EPI == 0) {
                qkv_store(m,     col, acc[mi][ni][0], acc[mi][ni][1]);
                qkv_store(m + 8, col, acc[mi][ni][2], acc[mi][ni][3]);
            } else {
                float b0v = bias[col], b1v = bias[col + 1];
                *(float2*)(outp + (size_t)m * Nc + col) =
                    make_float2(acc[mi][ni][0] + b0v, acc[mi][ni][1] + b1v);
                *(float2*)(outp + (size_t)(m + 8) * Nc + col) =
                    make_float2(acc[mi][ni][2] + b0v, acc[mi][ni][3] + b1v);
            }
        }
    }
}

// ---------------- flash attention: 128 q-rows/block, 64-key chunks ----------
__global__ __launch_bounds__(256) void flash_kernel() {
    __shared__ __half Ks[64 * 72];   // [key][d] pad 8
    __shared__ __half Vt[64 * 72];   // [d][key] pad 8 (transposed)

    const int tid = threadIdx.x;
    const int wid = tid >> 5, lane = tid & 31;
    const int g = lane >> 2, t = lane & 3;
    const int bh = blockIdx.y;
    const int b = bh >> 4, h = bh & 15;
    const int m0 = blockIdx.x * 128 + wid * 16;   // this warp's 16 q rows

    const __half* __restrict__ Qb = g_Q + (size_t)bh * Nq * Dd;
    const __half* __restrict__ Kb = g_K + (size_t)bh * Ll * Dd;
    const __half* __restrict__ Vb = g_V + (size_t)bh * Ll * Dd;

    // Q fragments (A-operand layout), kept in registers; Q pre-scaled by 0.125
    uint32_t qa[4][4];
#pragma unroll
    for (int ks = 0; ks < 4; ks++) {
        const __half* qp = Qb + (size_t)(m0 + g) * Dd + ks * 16 + 2 * t;
        qa[ks][0] = *(const uint32_t*)qp;
        qa[ks][1] = *(const uint32_t*)(qp + 8 * Dd);
        qa[ks][2] = *(const uint32_t*)(qp + 8);
        qa[ks][3] = *(const uint32_t*)(qp + 8 * Dd + 8);
    }

    float mrow[2] = {-1e30f, -1e30f};
    float lrow[2] = {0.f, 0.f};
    float o[8][4];
#pragma unroll
    for (int i = 0; i < 8; i++)
#pragma unroll
        for (int r = 0; r < 4; r++) o[i][r] = 0.f;

    const int nch = (Ll + 63) >> 6;   // 17
    for (int ch = 0; ch < nch; ch++) {
        const int kb = ch * 64;
        const int kc = min(64, Ll - kb);
        __syncthreads();
        // K chunk -> smem [key][d]
#pragma unroll
        for (int i = 0; i < 2; i++) {
            int idx = tid + i * 256;
            int row = idx >> 3, cc = idx & 7;
            float4 v = make_float4(0.f, 0.f, 0.f, 0.f);
            if (row < kc) v = *(const float4*)(Kb + (size_t)(kb + row) * Dd + cc * 8);
            *(float4*)(Ks + row * 72 + cc * 8) = v;
        }
        // V chunk -> smem transposed [d][key]
#pragma unroll
        for (int i = 0; i < 8; i++) {
            int idx = tid + i * 256;
            int row = idx >> 5, du = idx & 31;
            uint32_t v = 0;
            if (row < kc) v = *(const uint32_t*)(Vb + (size_t)(kb + row) * Dd + 2 * du);
            __half2 hv = *reinterpret_cast<__half2*>(&v);
            Vt[(2 * du) * 72 + row]     = __low2half(hv);
            Vt[(2 * du + 1) * 72 + row] = __high2half(hv);
        }
        __syncthreads();

        // S = Q K^T (scaled), 16 x 64 per warp
        float s[8][4];
#pragma unroll
        for (int i = 0; i < 8; i++)
#pragma unroll
            for (int r = 0; r < 4; r++) s[i][r] = 0.f;
#pragma unroll
        for (int ks = 0; ks < 4; ks++) {
#pragma unroll
            for (int nt = 0; nt < 8; nt++) {
                const __half* kp = Ks + (g + nt * 8) * 72 + ks * 16 + 2 * t;
                uint32_t b0 = *(const uint32_t*)kp;
                uint32_t b1 = *(const uint32_t*)(kp + 8);
                mma16816(s[nt], qa[ks][0], qa[ks][1], qa[ks][2], qa[ks][3], b0, b1);
            }
        }
        if (kc < 64) {
#pragma unroll
            for (int nt = 0; nt < 8; nt++) {
                int c0 = nt * 8 + 2 * t;
                if (c0 >= kc)     { s[nt][0] = -1e30f; s[nt][2] = -1e30f; }
                if (c0 + 1 >= kc) { s[nt][1] = -1e30f; s[nt][3] = -1e30f; }
            }
        }
        // online softmax update
        float mx0 = -1e30f, mx1 = -1e30f;
#pragma unroll
        for (int nt = 0; nt < 8; nt++) {
            mx0 = fmaxf(mx0, fmaxf(s[nt][0], s[nt][1]));
            mx1 = fmaxf(mx1, fmaxf(s[nt][2], s[nt][3]));
        }
        mx0 = qmax(mx0); mx1 = qmax(mx1);
        float mn0 = fmaxf(mrow[0], mx0), mn1 = fmaxf(mrow[1], mx1);
        float a0 = __expf(mrow[0] - mn0), a1 = __expf(mrow[1] - mn1);
        mrow[0] = mn0; mrow[1] = mn1;
        float sum0 = 0.f, sum1 = 0.f;
#pragma unroll
        for (int nt = 0; nt < 8; nt++) {
            s[nt][0] = __expf(s[nt][0] - mn0);
            s[nt][1] = __expf(s[nt][1] - mn0);
            s[nt][2] = __expf(s[nt][2] - mn1);
            s[nt][3] = __expf(s[nt][3] - mn1);
            sum0 += s[nt][0] + s[nt][1];
            sum1 += s[nt][2] + s[nt][3];
        }
        sum0 = qsum(sum0); sum1 = qsum(sum1);
        lrow[0] = lrow[0] * a0 + sum0;
        lrow[1] = lrow[1] * a1 + sum1;
#pragma unroll
        for (int nt = 0; nt < 8; nt++) {
            o[nt][0] *= a0; o[nt][1] *= a0; o[nt][2] *= a1; o[nt][3] *= a1;
        }
        // P fragments: S accumulator layout == A operand layout (pairs of n-tiles)
        uint32_t pa[4][4];
#pragma unroll
        for (int j = 0; j < 4; j++) {
            pa[j][0] = pack2(s[2 * j][0],     s[2 * j][1]);
            pa[j][1] = pack2(s[2 * j][2],     s[2 * j][3]);
            pa[j][2] = pack2(s[2 * j + 1][0], s[2 * j + 1][1]);
            pa[j][3] = pack2(s[2 * j + 1][2], s[2 * j + 1][3]);
        }
        // O += P @ V
#pragma unroll
        for (int j = 0; j < 4; j++) {
#pragma unroll
            for (int nt = 0; nt < 8; nt++) {
                const __half* vp = Vt + (g + nt * 8) * 72 + j * 16 + 2 * t;
                uint32_t b0 = *(const uint32_t*)vp;
                uint32_t b1 = *(const uint32_t*)(vp + 8);
                mma16816(o[nt], pa[j][0], pa[j][1], pa[j][2], pa[j][3], b0, b1);
            }
        }
    }

    // normalize + store to AO [b*N+n][h*64+d] (fp16)
    float inv0 = 1.f / lrow[0], inv1 = 1.f / lrow[1];
    size_t ro0 = ((size_t)b * Nq + (m0 + g)) * Cc + h * 64;
    size_t ro1 = ro0 + (size_t)8 * Cc;
#pragma unroll
    for (int nt = 0; nt < 8; nt++) {
        int c = nt * 8 + 2 * t;
        *(__half2*)(g_AO + ro0 + c) = __floats2half2_rn(o[nt][0] * inv0, o[nt][1] * inv0);
        *(__half2*)(g_AO + ro1 + c) = __floats2half2_rn(o[nt][2] * inv1, o[nt][3] * inv1);
    }
}

// ---------------- launch ----------------
extern "C" void kernel_launch(void* const* d_in, const int* in_sizes, int n_in,
                              void* d_out, int out_size) {
    const float* x  = (const float*)d_in[0];
    const float* pk = (const float*)d_in[1];
    const float* pv = (const float*)d_in[2];
    const float* wq = (const float*)d_in[3];
    const float* wp = (const float*)d_in[4];
    const float* bp = (const float*)d_in[5];
    float* out = (float*)d_out;

    (void)in_sizes; (void)n_in; (void)out_size;

    // 1. fp32 -> fp16 conversions (x, w_qkv, w_proj)
    int totq = NX4 + NQ4 + NP4;                   // 5242880 float4s
    convert_all<<<(totq + 255) / 256, 256>>>(x, wq, wp);

    // 2. prefix pk/pv scatter into K/V
    prefix_kernel<<<(Bb * Pp * Cc + 255) / 256, 256>>>(pk, pv);

    // 3. QKV projection GEMM with scatter epilogue
    {
        dim3 grid(3 * Cc / 128, Mr / 128);        // (24, 128)
        gemm_kernel<0><<<grid, 256>>>(nullptr, nullptr);
    }

    // 4. flash attention
    {
        dim3 grid(Nq / 128, Bb * Hh);             // (8, 256)
        flash_kernel<<<grid, 256>>>();
    }

    // 5. output projection + bias
    {
        dim3 grid(Cc / 128, Mr / 128);            // (8, 128)
        gemm_kernel<1><<<grid, 256>>>(out, bp);
    }
}

// round 8
// speedup vs baseline: 1.3637x; 1.3637x over previous
#include <cuda_runtime.h>
#include <cuda_fp16.h>
#include <cstdint>

#define DEVI static __device__ __forceinline__

// ---------------- problem dims ----------------
constexpr int Bb = 16, Nq = 1024, Cc = 1024, Hh = 16, Dd = 64, Pp = 16;
constexpr int Ll = Pp + Nq;       // 1040 keys
constexpr int Mr = Bb * Nq;       // 16384 token rows

// ---------------- scratch (device globals; no allocs allowed) ----------------
__device__ __half g_xh[Mr * Cc];            // x in fp16
__device__ __half g_wqkvh[Cc * 3 * Cc];     // w_qkv fp16
__device__ __half g_wprojh[Cc * Cc];        // w_proj fp16
__device__ __half g_Q[Bb * Hh * Nq * Dd];   // [bh][n][d], pre-scaled by 0.125
__device__ __half g_K[Bb * Hh * Ll * Dd];   // [bh][p+n][d]
__device__ __half g_V[Bb * Hh * Ll * Dd];   // [bh][p+n][d]
__device__ __half g_AO[Mr * Cc];            // attention out, [b*N+n][h*64+d]

// ---------------- small helpers ----------------
DEVI void cp16(void* smem, const void* gmem) {
    uint32_t s = (uint32_t)__cvta_generic_to_shared(smem);
    asm volatile("cp.async.cg.shared.global [%0], [%1], 16;\n" :: "r"(s), "l"(gmem));
}
DEVI void cp_commit() { asm volatile("cp.async.commit_group;\n"); }
template <int n> DEVI void cp_wait() { asm volatile("cp.async.wait_group %0;\n" :: "n"(n)); }

DEVI void mma16816(float* c, uint32_t a0, uint32_t a1, uint32_t a2, uint32_t a3,
                   uint32_t b0, uint32_t b1) {
    asm volatile(
        "mma.sync.aligned.m16n8k16.row.col.f32.f16.f16.f32 "
        "{%0,%1,%2,%3},{%4,%5,%6,%7},{%8,%9},{%0,%1,%2,%3};\n"
        : "+f"(c[0]), "+f"(c[1]), "+f"(c[2]), "+f"(c[3])
        : "r"(a0), "r"(a1), "r"(a2), "r"(a3), "r"(b0), "r"(b1));
}

DEVI void ldsm4(uint32_t& r0, uint32_t& r1, uint32_t& r2, uint32_t& r3, uint32_t a) {
    asm volatile("ldmatrix.sync.aligned.m8n8.x4.shared.b16 {%0,%1,%2,%3},[%4];\n"
                 : "=r"(r0), "=r"(r1), "=r"(r2), "=r"(r3) : "r"(a));
}
DEVI void ldsm4t(uint32_t& r0, uint32_t& r1, uint32_t& r2, uint32_t& r3, uint32_t a) {
    asm volatile("ldmatrix.sync.aligned.m8n8.x4.trans.shared.b16 {%0,%1,%2,%3},[%4];\n"
                 : "=r"(r0), "=r"(r1), "=r"(r2), "=r"(r3) : "r"(a));
}

DEVI uint32_t pack2(float x, float y) {
    __half2 h = __floats2half2_rn(x, y);
    return *reinterpret_cast<uint32_t*>(&h);
}
DEVI float qmax(float v) {
    v = fmaxf(v, __shfl_xor_sync(0xffffffffu, v, 1));
    v = fmaxf(v, __shfl_xor_sync(0xffffffffu, v, 2));
    return v;
}
DEVI float qsum(float v) {
    v += __shfl_xor_sync(0xffffffffu, v, 1);
    v += __shfl_xor_sync(0xffffffffu, v, 2);
    return v;
}

// ---------------- fp32 -> fp16 conversion (x, w_qkv, w_proj in one pass) ----
constexpr int NX4 = (Mr * Cc) / 4;
constexpr int NQ4 = (Cc * 3 * Cc) / 4;
constexpr int NP4 = (Cc * Cc) / 4;

__global__ void convert_all(const float* __restrict__ x,
                            const float* __restrict__ wq,
                            const float* __restrict__ wp) {
    int i = blockIdx.x * blockDim.x + threadIdx.x;
    const float4* src;
    __half2* dst;
    int j;
    if (i < NX4)            { src = (const float4*)x;  dst = (__half2*)g_xh;     j = i; }
    else if (i < NX4 + NQ4) { src = (const float4*)wq; dst = (__half2*)g_wqkvh;  j = i - NX4; }
    else if (i < NX4 + NQ4 + NP4) { src = (const float4*)wp; dst = (__half2*)g_wprojh; j = i - NX4 - NQ4; }
    else return;
    float4 v = src[j];
    dst[2 * j]     = __floats2half2_rn(v.x, v.y);
    dst[2 * j + 1] = __floats2half2_rn(v.z, v.w);
}

// ---------------- scatter prefix pk/pv into K/V heads ----------------
__global__ void prefix_kernel(const float* __restrict__ pk, const float* __restrict__ pv) {
    int i = blockIdx.x * blockDim.x + threadIdx.x;   // over B*P*C = 262144
    if (i >= Bb * Pp * Cc) return;
    int c = i & (Cc - 1);
    int bp = i >> 10;
    int p = bp & (Pp - 1);
    int b = bp >> 4;
    int h = c >> 6, d = c & 63;
    int o = ((b * Hh + h) * Ll + p) * Dd + d;
    g_K[o] = __float2half(pk[i]);
    g_V[o] = __float2half(pv[i]);
}

// ---------------- GEMM epilogue for QKV scatter ----------------
DEVI void qkv_store(int m, int col, float v0, float v1) {
    int b = m >> 10, n = m & 1023;
    int s = col >> 10, cc = col & 1023;
    int h = cc >> 6, d = cc & 63;
    if (s == 0) {
        __half2 hv = __floats2half2_rn(v0 * 0.125f, v1 * 0.125f);  // fold softmax scale
        *(__half2*)(g_Q + (((size_t)(b * Hh + h)) * Nq + n) * Dd + d) = hv;
    } else {
        __half2 hv = __floats2half2_rn(v0, v1);
        __half* base = (s == 1) ? g_K : g_V;
        *(__half2*)(base + (((size_t)(b * Hh + h)) * Ll + Pp + n) * Dd + d) = hv;
    }
}

// ---------------- tiled GEMM: 128x128x32, 256 thr, double-buffered cp.async --
// ldmatrix for all fragment loads. A smem [m][k] pad->40, B smem [k][n] pad->136.
template <int EPI>
__global__ __launch_bounds__(256) void gemm_kernel(float* __restrict__ outp,
                                                   const float* __restrict__ bias) {
    const __half* __restrict__ A  = (EPI == 0) ? g_xh : g_AO;
    const __half* __restrict__ Bm = (EPI == 0) ? g_wqkvh : g_wprojh;
    const int Nc = (EPI == 0) ? 3 * Cc : Cc;
    const int K  = Cc;

    __shared__ __half As[2][128 * 40];   // row stride 80B (conflict-free ldsm)
    __shared__ __half Bs[2][32 * 136];   // row stride 272B (conflict-free ldsm)

    const int tid = threadIdx.x;
    const int wid = tid >> 5, lane = tid & 31;
    const int g = lane >> 2, t = lane & 3;
    const int wm = wid >> 2, wn = wid & 3;         // 2x4 warp grid, warp tile 64x32
    const int mBase = blockIdx.y * 128, nBase = blockIdx.x * 128;

    float acc[4][4][4];
#pragma unroll
    for (int i = 0; i < 4; i++)
#pragma unroll
        for (int j = 0; j < 4; j++)
#pragma unroll
            for (int r = 0; r < 4; r++) acc[i][j][r] = 0.f;

    auto prefetch = [&](int kt, int buf) {
#pragma unroll
        for (int j = 0; j < 2; j++) {
            int ci = tid + j * 256;
            int row = ci >> 2, cc = ci & 3;
            cp16(&As[buf][row * 40 + cc * 8],
                 A + (size_t)(mBase + row) * K + kt * 32 + cc * 8);
        }
#pragma unroll
        for (int j = 0; j < 2; j++) {
            int ci = tid + j * 256;
            int row = ci >> 4, cc = ci & 15;
            cp16(&Bs[buf][row * 136 + cc * 8],
                 Bm + (size_t)(kt * 32 + row) * Nc + nBase + cc * 8);
        }
    };

    // ldmatrix per-lane base offsets
    const int lr = lane & 15, lc = (lane >> 4) & 1;

    const int nk = K >> 5;   // 32
    prefetch(0, 0);
    cp_commit();
    for (int kt = 0; kt < nk; kt++) {
        if (kt + 1 < nk) { prefetch(kt + 1, (kt + 1) & 1); cp_commit(); cp_wait<1>(); }
        else             { cp_wait<0>(); }
        __syncthreads();
        uint32_t abase = (uint32_t)__cvta_generic_to_shared(As[kt & 1])
                       + (wm * 64 + lr) * 80 + lc * 16;
        uint32_t bbase = (uint32_t)__cvta_generic_to_shared(Bs[kt & 1])
                       + lr * 272 + wn * 64 + lc * 16;
#pragma unroll
        for (int ks = 0; ks < 2; ks++) {
            uint32_t af[4][4];
#pragma unroll
            for (int mi = 0; mi < 4; mi++)
                ldsm4(af[mi][0], af[mi][1], af[mi][2], af[mi][3],
                      abase + mi * 16 * 80 + ks * 32);
            uint32_t bf[2][4];
#pragma unroll
            for (int nc = 0; nc < 2; nc++)
                ldsm4t(bf[nc][0], bf[nc][1], bf[nc][2], bf[nc][3],
                       bbase + ks * 16 * 272 + nc * 32);
#pragma unroll
            for (int ni = 0; ni < 4; ni++) {
                uint32_t b0 = bf[ni >> 1][(ni & 1) * 2];
                uint32_t b1 = bf[ni >> 1][(ni & 1) * 2 + 1];
#pragma unroll
                for (int mi = 0; mi < 4; mi++)
                    mma16816(acc[mi][ni], af[mi][0], af[mi][1], af[mi][2], af[mi][3], b0, b1);
            }
        }
        __syncthreads();
    }

    // epilogue
#pragma unroll
    for (int mi = 0; mi < 4; mi++) {
#pragma unroll
        for (int ni = 0; ni < 4; ni++) {
            int m = mBase + wm * 64 + mi * 16 + g;
            int col = nBase + wn * 32 + ni * 8 + 2 * t;
            if (EPI == 0) {
                qkv_store(m,     col, acc[mi][ni][0], acc[mi][ni][1]);
                qkv_store(m + 8, col, acc[mi][ni][2], acc[mi][ni][3]);
            } else {
                float b0v = bias[col], b1v = bias[col + 1];
                *(float2*)(outp + (size_t)m * Nc + col) =
                    make_float2(acc[mi][ni][0] + b0v, acc[mi][ni][1] + b1v);
                *(float2*)(outp + (size_t)(m + 8) * Nc + col) =
                    make_float2(acc[mi][ni][2] + b0v, acc[mi][ni][3] + b1v);
            }
        }
    }
}

// ---------------- flash attention: 128 q-rows/block, 64-key chunks ----------
// K and V both kept [key][d] in smem (stride 72 halves = 144B, conflict-free
// ldmatrix). QK^T B-frags via ldsm.x4 pairing (r0,r2)/(r1,r3); PV B-frags via
// ldsm.x4.trans. Double-buffered cp.async K/V loads overlap compute.
__global__ __launch_bounds__(256) void flash_kernel() {
    __shared__ __half KVs[2][2][64 * 72];   // [buf][K/V][key*72]

    const int tid = threadIdx.x;
    const int wid = tid >> 5, lane = tid & 31;
    const int g = lane >> 2, t = lane & 3;
    const int lr = lane & 15, lc = (lane >> 4) & 1;
    const int bh = blockIdx.y;
    const int b = bh >> 4, h = bh & 15;
    const int m0 = blockIdx.x * 128 + wid * 16;   // this warp's 16 q rows

    const __half* __restrict__ Qb = g_Q + (size_t)bh * Nq * Dd;
    const __half* __restrict__ Kb = g_K + (size_t)bh * Ll * Dd;
    const __half* __restrict__ Vb = g_V + (size_t)bh * Ll * Dd;

    // Q fragments (A-operand layout), Q pre-scaled by 0.125
    uint32_t qa[4][4];
#pragma unroll
    for (int ks = 0; ks < 4; ks++) {
        const __half* qp = Qb + (size_t)(m0 + g) * Dd + ks * 16 + 2 * t;
        qa[ks][0] = *(const uint32_t*)qp;
        qa[ks][1] = *(const uint32_t*)(qp + 8 * Dd);
        qa[ks][2] = *(const uint32_t*)(qp + 8);
        qa[ks][3] = *(const uint32_t*)(qp + 8 * Dd + 8);
    }

    float mrow[2] = {-1e30f, -1e30f};
    float lrow[2] = {0.f, 0.f};
    float o[8][4];
#pragma unroll
    for (int i = 0; i < 8; i++)
#pragma unroll
        for (int r = 0; r < 4; r++) o[i][r] = 0.f;

    auto prefetch = [&](int ch, int buf) {
        int kb = ch * 64;
#pragma unroll
        for (int i = 0; i < 2; i++) {
            int idx = tid + i * 256;
            int row = idx >> 3, cc = idx & 7;
            if (kb + row < Ll) {
                cp16(&KVs[buf][0][row * 72 + cc * 8], Kb + (size_t)(kb + row) * Dd + cc * 8);
                cp16(&KVs[buf][1][row * 72 + cc * 8], Vb + (size_t)(kb + row) * Dd + cc * 8);
            }
        }
    };

    const int nch = (Ll + 63) >> 6;   // 17
    prefetch(0, 0);
    cp_commit();
    for (int ch = 0; ch < nch; ch++) {
        const int kc = min(64, Ll - ch * 64);
        cp_wait<0>();
        __syncthreads();                          // buffer ch ready; prev compute done
        if (ch + 1 < nch) { prefetch(ch + 1, (ch + 1) & 1); cp_commit(); }

        uint32_t kbase = (uint32_t)__cvta_generic_to_shared(KVs[ch & 1][0])
                       + lr * 144 + lc * 16;
        uint32_t vbase = (uint32_t)__cvta_generic_to_shared(KVs[ch & 1][1])
                       + lr * 144 + lc * 16;

        // S = Q K^T (scaled), 16 x 64 per warp
        float s[8][4];
#pragma unroll
        for (int i = 0; i < 8; i++)
#pragma unroll
            for (int r = 0; r < 4; r++) s[i][r] = 0.f;
#pragma unroll
        for (int ntp = 0; ntp < 4; ntp++) {
#pragma unroll
            for (int ks = 0; ks < 4; ks++) {
                uint32_t r0, r1, r2, r3;
                ldsm4(r0, r1, r2, r3, kbase + ntp * 16 * 144 + ks * 32);
                // r0=(keys 0-7, d lo8), r1=(keys 8-15, d lo8),
                // r2=(keys 0-7, d hi8), r3=(keys 8-15, d hi8)
                // mma B wants same-key-group (k, k+8) pairs: (r0,r2) and (r1,r3)
                mma16816(s[2 * ntp],     qa[ks][0], qa[ks][1], qa[ks][2], qa[ks][3], r0, r2);
                mma16816(s[2 * ntp + 1], qa[ks][0], qa[ks][1], qa[ks][2], qa[ks][3], r1, r3);
            }
        }
        if (kc < 64) {   // stale smem rows beyond kc are masked here
#pragma unroll
            for (int nt = 0; nt < 8; nt++) {
                int c0 = nt * 8 + 2 * t;
                if (c0 >= kc)     { s[nt][0] = -1e30f; s[nt][2] = -1e30f; }
                if (c0 + 1 >= kc) { s[nt][1] = -1e30f; s[nt][3] = -1e30f; }
            }
        }
        // online softmax update
        float mx0 = -1e30f, mx1 = -1e30f;
#pragma unroll
        for (int nt = 0; nt < 8; nt++) {
            mx0 = fmaxf(mx0, fmaxf(s[nt][0], s[nt][1]));
            mx1 = fmaxf(mx1, fmaxf(s[nt][2], s[nt][3]));
        }
        mx0 = qmax(mx0); mx1 = qmax(mx1);
        float mn0 = fmaxf(mrow[0], mx0), mn1 = fmaxf(mrow[1], mx1);
        float a0 = __expf(mrow[0] - mn0), a1 = __expf(mrow[1] - mn1);
        mrow[0] = mn0; mrow[1] = mn1;
        float sum0 = 0.f, sum1 = 0.f;
#pragma unroll
        for (int nt = 0; nt < 8; nt++) {
            s[nt][0] = __expf(s[nt][0] - mn0);
            s[nt][1] = __expf(s[nt][1] - mn0);
            s[nt][2] = __expf(s[nt][2] - mn1);
            s[nt][3] = __expf(s[nt][3] - mn1);
            sum0 += s[nt][0] + s[nt][1];
            sum1 += s[nt][2] + s[nt][3];
        }
        sum0 = qsum(sum0); sum1 = qsum(sum1);
        lrow[0] = lrow[0] * a0 + sum0;
        lrow[1] = lrow[1] * a1 + sum1;
#pragma unroll
        for (int nt = 0; nt < 8; nt++) {
            o[nt][0] *= a0; o[nt][1] *= a0; o[nt][2] *= a1; o[nt][3] *= a1;
        }
        // P fragments: S accumulator layout == A operand layout (pairs of n-tiles)
        uint32_t pa[4][4];
#pragma unroll
        for (int j = 0; j < 4; j++) {
            pa[j][0] = pack2(s[2 * j][0],     s[2 * j][1]);
            pa[j][1] = pack2(s[2 * j][2],     s[2 * j][3]);
            pa[j][2] = pack2(s[2 * j + 1][0], s[2 * j + 1][1]);
            pa[j][3] = pack2(s[2 * j + 1][2], s[2 * j + 1][3]);
        }
        // O += P @ V  (V B-frags via ldmatrix.trans on [key][d] tile)
#pragma unroll
        for (int j = 0; j < 4; j++) {
#pragma unroll
            for (int dg = 0; dg < 4; dg++) {
                uint32_t v0, v1, v2, v3;
                ldsm4t(v0, v1, v2, v3, vbase + j * 16 * 144 + dg * 32);
                mma16816(o[2 * dg],     pa[j][0], pa[j][1], pa[j][2], pa[j][3], v0, v1);
                mma16816(o[2 * dg + 1], pa[j][0], pa[j][1], pa[j][2], pa[j][3], v2, v3);
            }
        }
        __syncthreads();   // all warps done with this buffer before it is refilled
    }

    // normalize + store to AO [b*N+n][h*64+d] (fp16)
    float inv0 = 1.f / lrow[0], inv1 = 1.f / lrow[1];
    size_t ro0 = ((size_t)b * Nq + (m0 + g)) * Cc + h * 64;
    size_t ro1 = ro0 + (size_t)8 * Cc;
#pragma unroll
    for (int nt = 0; nt < 8; nt++) {
        int c = nt * 8 + 2 * t;
        *(__half2*)(g_AO + ro0 + c) = __floats2half2_rn(o[nt][0] * inv0, o[nt][1] * inv0);
        *(__half2*)(g_AO + ro1 + c) = __floats2half2_rn(o[nt][2] * inv1, o[nt][3] * inv1);
    }
}

// ---------------- launch ----------------
extern "C" void kernel_launch(void* const* d_in, const int* in_sizes, int n_in,
                              void* d_out, int out_size) {
    const float* x  = (const float*)d_in[0];
    const float* pk = (const float*)d_in[1];
    const float* pv = (const float*)d_in[2];
    const float* wq = (const float*)d_in[3];
    const float* wp = (const float*)d_in[4];
    const float* bp = (const float*)d_in[5];
    float* out = (float*)d_out;

    (void)in_sizes; (void)n_in; (void)out_size;

    int totq = NX4 + NQ4 + NP4;
    convert_all<<<(totq + 255) / 256, 256>>>(x, wq, wp);
    prefix_kernel<<<(Bb * Pp * Cc + 255) / 256, 256>>>(pk, pv);
    {
        dim3 grid(3 * Cc / 128, Mr / 128);        // (24, 128)
        gemm_kernel<0><<<grid, 256>>>(nullptr, nullptr);
    }
    {
        dim3 grid(Nq / 128, Bb * Hh);             // (8, 256)
        flash_kernel<<<grid, 256>>>();
    }
    {
        dim3 grid(Cc / 128, Mr / 128);            // (8, 128)
        gemm_kernel<1><<<grid, 256>>>(out, bp);
    }
}